// round 1
// baseline (speedup 1.0000x reference)
#include <cuda_runtime.h>
#include <cuda_bf16.h>

// DynMorphConv2d: out[b,c,h,w] = max_{ki,kj in 0..2} ( xpad[b,c,h+ki,w+kj]
//                                 + sigmoid(x[b,c,h,w]*gw[c]+gb[c]) * k[c,ki*3+kj] )
// B=8, C=192, H=W=128, zero padding (pad taps contribute 0 + theta*k).
//
// Strategy: HBM-bound streaming. One CTA per half-plane (64 rows + 2 halo
// rows staged in static smem), warp-per-row float4 lanes, shuffles for the
// +-1 column neighbors (lane edges == plane edges == zero pad).

#define CH      192
#define HH      128
#define WW      128
#define RPB     64          // output rows per block
#define SROWS   (RPB + 2)   // staged rows incl. halo
#define NTHR    256

__global__ __launch_bounds__(NTHR, 4)
void dynmorph_kernel(const float* __restrict__ x,
                     const float* __restrict__ kern,
                     const float* __restrict__ gw,
                     const float* __restrict__ gb,
                     float* __restrict__ out)
{
    __shared__ float sm[SROWS][WW];   // 66*128*4 = 33792 B

    const int bx    = blockIdx.x;
    const int plane = bx >> 1;        // b*C + c
    const int half  = bx & 1;
    const int c     = plane % CH;
    const int r0    = half * RPB;

    const float* xp = x   + (size_t)plane * (HH * WW);
    float*       op = out + (size_t)plane * (HH * WW);

    const int t = threadIdx.x;

    // ---- stage 66 rows (with zero-filled OOB halos) into smem, float4 ----
    const int NF4 = SROWS * (WW / 4);         // 66*32 = 2112
    for (int idx = t; idx < NF4; idx += NTHR) {
        const int sr = idx >> 5;              // 0..65
        const int cl = idx & 31;              // float4 column
        const int gr = r0 - 1 + sr;           // global row
        float4 v = make_float4(0.f, 0.f, 0.f, 0.f);
        if (gr >= 0 && gr < HH)
            v = __ldg(reinterpret_cast<const float4*>(xp + (size_t)gr * WW) + cl);
        reinterpret_cast<float4*>(sm[sr])[cl] = v;
    }

    // ---- per-channel params (broadcast via L1) ----
    float kk[9];
#pragma unroll
    for (int i = 0; i < 9; i++) kk[i] = __ldg(kern + c * 9 + i);
    const float gwv = __ldg(gw + c);
    const float gbv = __ldg(gb + c);

    __syncthreads();

    const int lane = t & 31;

    // ---- compute: 64 rows x 32 float4 cells = 2048 cells / 256 thr = 8 ----
#pragma unroll
    for (int i = 0; i < (RPB * (WW / 4)) / NTHR; i++) {
        const int idx = t + i * NTHR;
        const int lr  = idx >> 5;             // local output row 0..63
        // All lanes of a warp share lr (idx/32 is lane-invariant), so the
        // warp covers the full 128-wide row -> shuffles give +-1 neighbors.

        const float4 a  = reinterpret_cast<const float4*>(sm[lr    ])[lane]; // row above
        const float4 b4 = reinterpret_cast<const float4*>(sm[lr + 1])[lane]; // center row
        const float4 cc = reinterpret_cast<const float4*>(sm[lr + 2])[lane]; // row below

        float ra[6], rb[6], rc[6];
        ra[1]=a.x;  ra[2]=a.y;  ra[3]=a.z;  ra[4]=a.w;
        rb[1]=b4.x; rb[2]=b4.y; rb[3]=b4.z; rb[4]=b4.w;
        rc[1]=cc.x; rc[2]=cc.y; rc[3]=cc.z; rc[4]=cc.w;

        // left neighbor (col 4*lane-1): lane-1's .w ; lane 0 -> zero pad
        ra[0] = __shfl_up_sync(0xffffffffu, a.w,  1);
        rb[0] = __shfl_up_sync(0xffffffffu, b4.w, 1);
        rc[0] = __shfl_up_sync(0xffffffffu, cc.w, 1);
        // right neighbor (col 4*lane+4): lane+1's .x ; lane 31 -> zero pad
        ra[5] = __shfl_down_sync(0xffffffffu, a.x,  1);
        rb[5] = __shfl_down_sync(0xffffffffu, b4.x, 1);
        rc[5] = __shfl_down_sync(0xffffffffu, cc.x, 1);
        if (lane == 0)  { ra[0] = 0.f; rb[0] = 0.f; rc[0] = 0.f; }
        if (lane == 31) { ra[5] = 0.f; rb[5] = 0.f; rc[5] = 0.f; }

        float ov[4];
#pragma unroll
        for (int e = 0; e < 4; e++) {
            const float z  = fmaf(rb[e + 1], gwv, gbv);
            const float th = 1.f / (1.f + __expf(-z));
            float m;
            m = fmaf(th, kk[0], ra[e    ]);
            m = fmaxf(m, fmaf(th, kk[1], ra[e + 1]));
            m = fmaxf(m, fmaf(th, kk[2], ra[e + 2]));
            m = fmaxf(m, fmaf(th, kk[3], rb[e    ]));
            m = fmaxf(m, fmaf(th, kk[4], rb[e + 1]));
            m = fmaxf(m, fmaf(th, kk[5], rb[e + 2]));
            m = fmaxf(m, fmaf(th, kk[6], rc[e    ]));
            m = fmaxf(m, fmaf(th, kk[7], rc[e + 1]));
            m = fmaxf(m, fmaf(th, kk[8], rc[e + 2]));
            ov[e] = m;
        }

        float4 o = make_float4(ov[0], ov[1], ov[2], ov[3]);
        reinterpret_cast<float4*>(op + (size_t)(r0 + lr) * WW)[lane] = o;
    }
}

extern "C" void kernel_launch(void* const* d_in, const int* in_sizes, int n_in,
                              void* d_out, int out_size)
{
    const float* x    = (const float*)d_in[0];   // [8,192,128,128]
    const float* kern = (const float*)d_in[1];   // [192,9]
    const float* gwp  = (const float*)d_in[2];   // [192]
    const float* gbp  = (const float*)d_in[3];   // [192]
    float*       out  = (float*)d_out;

    const int B = in_sizes[0] / (CH * HH * WW);  // 8
    const int grid = B * CH * 2;                 // 3072 half-plane blocks

    dynmorph_kernel<<<grid, NTHR>>>(x, kern, gwp, gbp, out);
}

// round 3
// speedup vs baseline: 1.2360x; 1.2360x over previous
#include <cuda_runtime.h>
#include <cuda_bf16.h>

// DynMorphConv2d: out[b,c,h,w] = max_{ki,kj} ( xpad[b,c,h+ki,w+kj]
//                                + sigmoid(x*gw[c]+gb[c]) * k[c,ki*3+kj] )
// B=8, C=192, H=W=128, zero pad.
//
// R2: register-rolling rows, no smem, no barriers. Warp = 32-row strip of one
// plane; 3 expanded rows live in registers; 1 coalesced float4 LDG per new
// row (prefetched one iteration ahead); 2 shuffles per new row for the +-1
// column halo (lane edges == plane edges == zero pad).

#define CH    192
#define HH    128
#define WW    128
#define RPW   32          // rows per warp
#define NWARP 4
#define NTHR  (NWARP * 32)

__device__ __forceinline__ float4 ldrow(const float* __restrict__ xp,
                                        int gr, int lane)
{
    if ((unsigned)gr < (unsigned)HH)
        return __ldg(reinterpret_cast<const float4*>(xp + (size_t)gr * WW) + lane);
    return make_float4(0.f, 0.f, 0.f, 0.f);
}

__device__ __forceinline__ void expand(float4 v, int lane, float* __restrict__ r)
{
    r[1] = v.x; r[2] = v.y; r[3] = v.z; r[4] = v.w;
    r[0] = __shfl_up_sync(0xffffffffu, v.w, 1);    // col-1 from lane-1
    r[5] = __shfl_down_sync(0xffffffffu, v.x, 1);  // col+4 from lane+1
    if (lane == 0)  r[0] = 0.f;
    if (lane == 31) r[5] = 0.f;
}

__global__ __launch_bounds__(NTHR, 8)
void dynmorph_kernel(const float* __restrict__ x,
                     const float* __restrict__ kern,
                     const float* __restrict__ gw,
                     const float* __restrict__ gb,
                     float* __restrict__ out)
{
    const int plane = blockIdx.x;            // b*C + c
    const int c     = plane % CH;
    const int warp  = threadIdx.x >> 5;
    const int lane  = threadIdx.x & 31;
    const int rs    = warp * RPW;            // first output row of this warp

    const float* xp = x   + (size_t)plane * (HH * WW);
    float*       op = out + (size_t)plane * (HH * WW);

    float kk[9];
#pragma unroll
    for (int i = 0; i < 9; i++) kk[i] = __ldg(kern + c * 9 + i);
    const float gwv = __ldg(gw + c);
    const float gbv = __ldg(gb + c);

    // prime the 3-row window: rows rs-1 (halo) and rs
    float a[6], b[6], cr[6];
    expand(ldrow(xp, rs - 1, lane), lane, a);
    expand(ldrow(xp, rs,     lane), lane, b);
    float4 vC = ldrow(xp, rs + 1, lane);

#pragma unroll 4
    for (int r = 0; r < RPW; r++) {
        // prefetch the row needed next iteration (OOB -> zeros, harmless)
        float4 vN = ldrow(xp, rs + r + 2, lane);

        expand(vC, lane, cr);

        float ov[4];
#pragma unroll
        for (int e = 0; e < 4; e++) {
            const float z  = fmaf(b[e + 1], gwv, gbv);
            const float th = 1.f / (1.f + __expf(-z));
            float m;
            m = fmaf(th, kk[0], a[e    ]);
            m = fmaxf(m, fmaf(th, kk[1], a[e + 1]));
            m = fmaxf(m, fmaf(th, kk[2], a[e + 2]));
            m = fmaxf(m, fmaf(th, kk[3], b[e    ]));
            m = fmaxf(m, fmaf(th, kk[4], b[e + 1]));
            m = fmaxf(m, fmaf(th, kk[5], b[e + 2]));
            m = fmaxf(m, fmaf(th, kk[6], cr[e    ]));
            m = fmaxf(m, fmaf(th, kk[7], cr[e + 1]));
            m = fmaxf(m, fmaf(th, kk[8], cr[e + 2]));
            ov[e] = m;
        }

        reinterpret_cast<float4*>(op + (size_t)(rs + r) * WW)[lane] =
            make_float4(ov[0], ov[1], ov[2], ov[3]);

        // rotate window (renamed away under unroll)
#pragma unroll
        for (int i = 0; i < 6; i++) { a[i] = b[i]; b[i] = cr[i]; }
        vC = vN;
    }
}

extern "C" void kernel_launch(void* const* d_in, const int* in_sizes, int n_in,
                              void* d_out, int out_size)
{
    const float* x    = (const float*)d_in[0];   // [8,192,128,128]
    const float* kern = (const float*)d_in[1];   // [192,9]
    const float* gwp  = (const float*)d_in[2];   // [192]
    const float* gbp  = (const float*)d_in[3];   // [192]
    float*       out  = (float*)d_out;

    const int B = in_sizes[0] / (CH * HH * WW);  // 8
    const int grid = B * CH;                     // 1536 plane blocks

    dynmorph_kernel<<<grid, NTHR>>>(x, kern, gwp, gbp, out);
}

// round 4
// speedup vs baseline: 1.5395x; 1.2456x over previous
#include <cuda_runtime.h>
#include <cuda_bf16.h>

// DynMorphConv2d: out[b,c,h,w] = max_{ki,kj} ( xpad[b,c,h+ki,w+kj]
//                                + sigmoid(x*gw[c]+gb[c]) * k[c,ki*3+kj] )
// B=8, C=192, H=W=128, zero pad.
//
// R3: issue-bound -> shrink instruction stream.
//  - sigmoid via tanh.approx.f32 (1 MUFU instead of 2 + extra ops)
//  - packed fma.rn.f32x2 for taps + gate (elements processed in pairs)
//  - rows kept as 5 overlapping packed pairs, built once per loaded row
//  - 3-wide max trees (FMNMX3-fusable), 2-deep row prefetch

#define CH    192
#define HH    128
#define WW    128
#define RPW   32
#define NTHR  128

typedef unsigned long long u64;

__device__ __forceinline__ u64 pack2(float lo, float hi) {
    u64 r; asm("mov.b64 %0,{%1,%2};" : "=l"(r) : "f"(lo), "f"(hi)); return r;
}
__device__ __forceinline__ void unpack2(u64 v, float& lo, float& hi) {
    asm("mov.b64 {%0,%1},%2;" : "=f"(lo), "=f"(hi) : "l"(v));
}
__device__ __forceinline__ u64 ffma2(u64 a, u64 b, u64 c) {
    u64 d; asm("fma.rn.f32x2 %0,%1,%2,%3;" : "=l"(d) : "l"(a), "l"(b), "l"(c));
    return d;
}
__device__ __forceinline__ float tanha(float x) {
    float y; asm("tanh.approx.f32 %0,%1;" : "=f"(y) : "f"(x)); return y;
}

struct Row { u64 p01, p12, p23, p34, p45; };  // overlapping pairs (r[i],r[i+1])

__device__ __forceinline__ float4 ldrow(const float* __restrict__ xp,
                                        int gr, int lane)
{
    if ((unsigned)gr < (unsigned)HH)
        return __ldg(reinterpret_cast<const float4*>(xp + (size_t)gr * WW) + lane);
    return make_float4(0.f, 0.f, 0.f, 0.f);
}

__device__ __forceinline__ Row expand(float4 v, int lane)
{
    float l = __shfl_up_sync(0xffffffffu, v.w, 1);    // col-1
    float r = __shfl_down_sync(0xffffffffu, v.x, 1);  // col+4
    if (lane == 0)  l = 0.f;
    if (lane == 31) r = 0.f;
    Row R;
    R.p01 = pack2(l,   v.x);
    R.p12 = pack2(v.x, v.y);
    R.p23 = pack2(v.y, v.z);
    R.p34 = pack2(v.z, v.w);
    R.p45 = pack2(v.w, r);
    return R;
}

__global__ __launch_bounds__(NTHR, 5)
void dynmorph_kernel(const float* __restrict__ x,
                     const float* __restrict__ kern,
                     const float* __restrict__ gw,
                     const float* __restrict__ gb,
                     float* __restrict__ out)
{
    const int plane = blockIdx.x;            // b*C + c
    const int c     = plane % CH;
    const int warp  = threadIdx.x >> 5;
    const int lane  = threadIdx.x & 31;
    const int rs    = warp * RPW;

    const float* xp = x   + (size_t)plane * (HH * WW);
    float*       op = out + (size_t)plane * (HH * WW);

    // dup-packed per-channel constants
    u64 k2[9];
#pragma unroll
    for (int i = 0; i < 9; i++) {
        const float kv = __ldg(kern + c * 9 + i);
        k2[i] = pack2(kv, kv);
    }
    const float gwh = 0.5f * __ldg(gw + c);   // fold tanh half-angle
    const float gbh = 0.5f * __ldg(gb + c);
    const u64 gwh2  = pack2(gwh, gwh);
    const u64 gbh2  = pack2(gbh, gbh);
    const u64 half2 = pack2(0.5f, 0.5f);

    // prime 3-row window + 2-deep prefetch
    Row A = expand(ldrow(xp, rs - 1, lane), lane);
    Row B = expand(ldrow(xp, rs,     lane), lane);
    float4 vC = ldrow(xp, rs + 1, lane);
    float4 vN = ldrow(xp, rs + 2, lane);

#pragma unroll 4
    for (int r = 0; r < RPW; r++) {
        float4 vN2 = ldrow(xp, rs + r + 3, lane);   // 2 iterations ahead

        Row C = expand(vC, lane);

        // gate: th = 0.5 + 0.5*tanh(x*gw/2 + gb/2), packed in pairs
        float z0, z1, z2, z3;
        unpack2(ffma2(B.p12, gwh2, gbh2), z0, z1);
        unpack2(ffma2(B.p34, gwh2, gbh2), z2, z3);
        const u64 th01 = ffma2(pack2(tanha(z0), tanha(z1)), half2, half2);
        const u64 th23 = ffma2(pack2(tanha(z2), tanha(z3)), half2, half2);

        // 9 taps per element, computed 2 elements at a time
        float s[4][9];
        unpack2(ffma2(th01, k2[0], A.p01), s[0][0], s[1][0]);
        unpack2(ffma2(th01, k2[1], A.p12), s[0][1], s[1][1]);
        unpack2(ffma2(th01, k2[2], A.p23), s[0][2], s[1][2]);
        unpack2(ffma2(th01, k2[3], B.p01), s[0][3], s[1][3]);
        unpack2(ffma2(th01, k2[4], B.p12), s[0][4], s[1][4]);
        unpack2(ffma2(th01, k2[5], B.p23), s[0][5], s[1][5]);
        unpack2(ffma2(th01, k2[6], C.p01), s[0][6], s[1][6]);
        unpack2(ffma2(th01, k2[7], C.p12), s[0][7], s[1][7]);
        unpack2(ffma2(th01, k2[8], C.p23), s[0][8], s[1][8]);

        unpack2(ffma2(th23, k2[0], A.p23), s[2][0], s[3][0]);
        unpack2(ffma2(th23, k2[1], A.p34), s[2][1], s[3][1]);
        unpack2(ffma2(th23, k2[2], A.p45), s[2][2], s[3][2]);
        unpack2(ffma2(th23, k2[3], B.p23), s[2][3], s[3][3]);
        unpack2(ffma2(th23, k2[4], B.p34), s[2][4], s[3][4]);
        unpack2(ffma2(th23, k2[5], B.p45), s[2][5], s[3][5]);
        unpack2(ffma2(th23, k2[6], C.p23), s[2][6], s[3][6]);
        unpack2(ffma2(th23, k2[7], C.p34), s[2][7], s[3][7]);
        unpack2(ffma2(th23, k2[8], C.p45), s[2][8], s[3][8]);

        float ov[4];
#pragma unroll
        for (int e = 0; e < 4; e++) {
            const float m0 = fmaxf(fmaxf(s[e][0], s[e][1]), s[e][2]);
            const float m1 = fmaxf(fmaxf(s[e][3], s[e][4]), s[e][5]);
            const float m2 = fmaxf(fmaxf(s[e][6], s[e][7]), s[e][8]);
            ov[e] = fmaxf(fmaxf(m0, m1), m2);
        }

        reinterpret_cast<float4*>(op + (size_t)(rs + r) * WW)[lane] =
            make_float4(ov[0], ov[1], ov[2], ov[3]);

        A = B; B = C;           // renamed away under unroll
        vC = vN; vN = vN2;
    }
}

extern "C" void kernel_launch(void* const* d_in, const int* in_sizes, int n_in,
                              void* d_out, int out_size)
{
    const float* x    = (const float*)d_in[0];   // [8,192,128,128]
    const float* kern = (const float*)d_in[1];   // [192,9]
    const float* gwp  = (const float*)d_in[2];   // [192]
    const float* gbp  = (const float*)d_in[3];   // [192]
    float*       out  = (float*)d_out;

    const int B = in_sizes[0] / (CH * HH * WW);  // 8
    const int grid = B * CH;                     // 1536 plane blocks

    dynmorph_kernel<<<grid, NTHR>>>(x, kern, gwp, gbp, out);
}

// round 6
// speedup vs baseline: 1.7189x; 1.1165x over previous
#include <cuda_runtime.h>
#include <cuda_bf16.h>

// DynMorphConv2d: out[b,c,h,w] = max_{ki,kj} ( xpad[b,c,h+ki,w+kj]
//                                + sigmoid(x*gw[c]+gb[c]) * k[c,ki*3+kj] )
// B=8, C=192, H=W=128, zero pad.
//
// R5: R4 structure, but running max done on scalar halves (FMNMX) since
// max.f32x2 doesn't exist in PTX. Unpack of f32x2 results is register-pair
// aliasing (free). Packed FFMA2 taps, tanh.approx gate, no s[4][9] array.

#define CH    192
#define HH    128
#define WW    128
#define RPW   32
#define NTHR  128

typedef unsigned long long u64;

__device__ __forceinline__ u64 pack2(float lo, float hi) {
    u64 r; asm("mov.b64 %0,{%1,%2};" : "=l"(r) : "f"(lo), "f"(hi)); return r;
}
__device__ __forceinline__ void unpack2(u64 v, float& lo, float& hi) {
    asm("mov.b64 {%0,%1},%2;" : "=f"(lo), "=f"(hi) : "l"(v));
}
__device__ __forceinline__ u64 ffma2(u64 a, u64 b, u64 c) {
    u64 d; asm("fma.rn.f32x2 %0,%1,%2,%3;" : "=l"(d) : "l"(a), "l"(b), "l"(c));
    return d;
}
__device__ __forceinline__ float tanha(float x) {
    float y; asm("tanh.approx.f32 %0,%1;" : "=f"(y) : "f"(x)); return y;
}

struct Row { u64 p01, p12, p23, p34, p45; };  // overlapping pairs (r[i],r[i+1])

__device__ __forceinline__ float4 ldrow(const float* __restrict__ xp,
                                        int gr, int lane)
{
    if ((unsigned)gr < (unsigned)HH)
        return __ldg(reinterpret_cast<const float4*>(xp + (size_t)gr * WW) + lane);
    return make_float4(0.f, 0.f, 0.f, 0.f);
}

__device__ __forceinline__ Row expand(float4 v, int lane)
{
    float l = __shfl_up_sync(0xffffffffu, v.w, 1);    // col-1
    float r = __shfl_down_sync(0xffffffffu, v.x, 1);  // col+4
    if (lane == 0)  l = 0.f;
    if (lane == 31) r = 0.f;
    Row R;
    R.p01 = pack2(l,   v.x);
    R.p12 = pack2(v.x, v.y);
    R.p23 = pack2(v.y, v.z);
    R.p34 = pack2(v.z, v.w);
    R.p45 = pack2(v.w, r);
    return R;
}

// tap: d = th*k + row (packed), then fold halves into scalar running maxes
__device__ __forceinline__ void tapmax(u64 th, u64 k, u64 row,
                                       float& mlo, float& mhi)
{
    float lo, hi;
    unpack2(ffma2(th, k, row), lo, hi);   // unpack is free (reg-pair alias)
    mlo = fmaxf(mlo, lo);
    mhi = fmaxf(mhi, hi);
}

__global__ __launch_bounds__(NTHR, 6)
void dynmorph_kernel(const float* __restrict__ x,
                     const float* __restrict__ kern,
                     const float* __restrict__ gw,
                     const float* __restrict__ gb,
                     float* __restrict__ out)
{
    const int plane = blockIdx.x;            // b*C + c
    const int c     = plane % CH;
    const int warp  = threadIdx.x >> 5;
    const int lane  = threadIdx.x & 31;
    const int rs    = warp * RPW;

    const float* xp = x   + (size_t)plane * (HH * WW);
    float*       op = out + (size_t)plane * (HH * WW);

    // dup-packed per-channel constants
    u64 k2[9];
#pragma unroll
    for (int i = 0; i < 9; i++) {
        const float kv = __ldg(kern + c * 9 + i);
        k2[i] = pack2(kv, kv);
    }
    const float gwh = 0.5f * __ldg(gw + c);   // fold tanh half-angle
    const float gbh = 0.5f * __ldg(gb + c);
    const u64 gwh2  = pack2(gwh, gwh);
    const u64 gbh2  = pack2(gbh, gbh);
    const u64 half2 = pack2(0.5f, 0.5f);

    // prime 3-row window + 2-deep prefetch
    Row A = expand(ldrow(xp, rs - 1, lane), lane);
    Row B = expand(ldrow(xp, rs,     lane), lane);
    float4 vC = ldrow(xp, rs + 1, lane);
    float4 vN = ldrow(xp, rs + 2, lane);

#pragma unroll 4
    for (int r = 0; r < RPW; r++) {
        float4 vN2 = ldrow(xp, rs + r + 3, lane);   // 2 iterations ahead

        Row C = expand(vC, lane);

        // gate: th = 0.5 + 0.5*tanh(x*gw/2 + gb/2), packed in pairs
        float z0, z1, z2, z3;
        unpack2(ffma2(B.p12, gwh2, gbh2), z0, z1);
        unpack2(ffma2(B.p34, gwh2, gbh2), z2, z3);
        const u64 th01 = ffma2(pack2(tanha(z0), tanha(z1)), half2, half2);
        const u64 th23 = ffma2(pack2(tanha(z2), tanha(z3)), half2, half2);

        // elements 0,1: running max over 9 taps
        float m0, m1, m2, m3;
        {
            float lo, hi;
            unpack2(ffma2(th01, k2[0], A.p01), lo, hi);
            m0 = lo; m1 = hi;
        }
        tapmax(th01, k2[1], A.p12, m0, m1);
        tapmax(th01, k2[2], A.p23, m0, m1);
        tapmax(th01, k2[3], B.p01, m0, m1);
        tapmax(th01, k2[4], B.p12, m0, m1);
        tapmax(th01, k2[5], B.p23, m0, m1);
        tapmax(th01, k2[6], C.p01, m0, m1);
        tapmax(th01, k2[7], C.p12, m0, m1);
        tapmax(th01, k2[8], C.p23, m0, m1);

        // elements 2,3
        {
            float lo, hi;
            unpack2(ffma2(th23, k2[0], A.p23), lo, hi);
            m2 = lo; m3 = hi;
        }
        tapmax(th23, k2[1], A.p34, m2, m3);
        tapmax(th23, k2[2], A.p45, m2, m3);
        tapmax(th23, k2[3], B.p23, m2, m3);
        tapmax(th23, k2[4], B.p34, m2, m3);
        tapmax(th23, k2[5], B.p45, m2, m3);
        tapmax(th23, k2[6], C.p23, m2, m3);
        tapmax(th23, k2[7], C.p34, m2, m3);
        tapmax(th23, k2[8], C.p45, m2, m3);

        reinterpret_cast<float4*>(op + (size_t)(rs + r) * WW)[lane] =
            make_float4(m0, m1, m2, m3);

        A = B; B = C;           // renamed away under unroll
        vC = vN; vN = vN2;
    }
}

extern "C" void kernel_launch(void* const* d_in, const int* in_sizes, int n_in,
                              void* d_out, int out_size)
{
    const float* x    = (const float*)d_in[0];   // [8,192,128,128]
    const float* kern = (const float*)d_in[1];   // [192,9]
    const float* gwp  = (const float*)d_in[2];   // [192]
    const float* gbp  = (const float*)d_in[3];   // [192]
    float*       out  = (float*)d_out;

    const int B = in_sizes[0] / (CH * HH * WW);  // 8
    const int grid = B * CH;                     // 1536 plane blocks

    dynmorph_kernel<<<grid, NTHR>>>(x, kern, gwp, gbp, out);
}